// round 1
// baseline (speedup 1.0000x reference)
#include <cuda_runtime.h>
#include <math.h>

#define NSTEP 8192
#define NMOD  4096
#define DIM   1024
#define INVT  (1.0f / 0.07f)

// ---------------- device scratch (static, no allocation) ----------------
__device__ float    g_inva[NSTEP];
__device__ float    g_invb[NMOD];
__device__ float    g_invc[NMOD];
__device__ unsigned g_negmax[NSTEP];   // ordered-uint encoded float max
__device__ float    g_perstep[NSTEP];
__device__ float    g_wsum[NSTEP];

// monotone float <-> uint encoding for atomicMax on signed floats
__device__ __forceinline__ unsigned fenc(float f) {
    unsigned u = __float_as_uint(f);
    return (u & 0x80000000u) ? ~u : (u | 0x80000000u);
}
__device__ __forceinline__ float fdec(unsigned u) {
    return (u & 0x80000000u) ? __uint_as_float(u & 0x7FFFFFFFu)
                             : __uint_as_float(~u);
}

// ---------------- init (every launch: deterministic) ----------------
__global__ void init_kernel() {
    int i = blockIdx.x * 256 + threadIdx.x;
    if (i < NSTEP) g_negmax[i] = 0u;   // 0 < fenc(x) for all finite x
}

// ---------------- inverse norms ----------------
template <int WHICH>
__global__ void inv_norm_kernel(const float* __restrict__ X) {
    __shared__ float red[256];
    const int row = blockIdx.x;
    const int tid = threadIdx.x;
    const float4* p = reinterpret_cast<const float4*>(X + (size_t)row * DIM);
    float4 v = p[tid];                       // 1024 = 256 threads * 4 floats
    float s = v.x * v.x + v.y * v.y + v.z * v.z + v.w * v.w;
    red[tid] = s;
    __syncthreads();
    for (int off = 128; off > 0; off >>= 1) {
        if (tid < off) red[tid] += red[tid + off];
        __syncthreads();
    }
    if (tid == 0) {
        float inv = 1.0f / fmaxf(sqrtf(red[0]), 1e-8f);
        if (WHICH == 0)      g_inva[row] = inv;
        else if (WHICH == 1) g_invb[row] = inv;
        else                 g_invc[row] = inv;
    }
}

// ---------------- SGEMM (NT): R = A * B^T ----------------
// MODE 0: write raw dots into Rout (the attention region of d_out)
// MODE 1: epilogue computes per-row max of R * invc[col] -> atomicMax
template <int MODE>
__global__ __launch_bounds__(256, 2)
void gemm_nt_kernel(const float* __restrict__ A, const float* __restrict__ B,
                    float* __restrict__ Rout) {
    __shared__ float As[16][128];
    __shared__ float Bs[16][128];
    const int tid = threadIdx.x;
    const int tx = tid & 15;         // column group
    const int ty = tid >> 4;         // row group
    const int rowBase = blockIdx.y * 128;
    const int colBase = blockIdx.x * 128;

    float acc[8][8];
#pragma unroll
    for (int i = 0; i < 8; i++)
#pragma unroll
        for (int j = 0; j < 8; j++) acc[i][j] = 0.0f;

    const float* Ab = A + (size_t)rowBase * DIM;
    const float* Bb = B + (size_t)colBase * DIM;

    for (int k0 = 0; k0 < DIM; k0 += 16) {
        // cooperative loads: 128 rows x 16 k each for A and B (transposed store)
#pragma unroll
        for (int l = 0; l < 2; l++) {
            int id = tid + l * 256;
            int r  = id >> 2;
            int kq = (id & 3) << 2;
            float4 va = *reinterpret_cast<const float4*>(Ab + (size_t)r * DIM + k0 + kq);
            As[kq + 0][r] = va.x; As[kq + 1][r] = va.y;
            As[kq + 2][r] = va.z; As[kq + 3][r] = va.w;
            float4 vb = *reinterpret_cast<const float4*>(Bb + (size_t)r * DIM + k0 + kq);
            Bs[kq + 0][r] = vb.x; Bs[kq + 1][r] = vb.y;
            Bs[kq + 2][r] = vb.z; Bs[kq + 3][r] = vb.w;
        }
        __syncthreads();
#pragma unroll
        for (int k = 0; k < 16; k++) {
            float4 a0 = *reinterpret_cast<const float4*>(&As[k][ty * 8]);
            float4 a1 = *reinterpret_cast<const float4*>(&As[k][ty * 8 + 4]);
            float4 b0 = *reinterpret_cast<const float4*>(&Bs[k][tx * 8]);
            float4 b1 = *reinterpret_cast<const float4*>(&Bs[k][tx * 8 + 4]);
            float av[8] = {a0.x, a0.y, a0.z, a0.w, a1.x, a1.y, a1.z, a1.w};
            float bv[8] = {b0.x, b0.y, b0.z, b0.w, b1.x, b1.y, b1.z, b1.w};
#pragma unroll
            for (int i = 0; i < 8; i++)
#pragma unroll
                for (int j = 0; j < 8; j++)
                    acc[i][j] += av[i] * bv[j];
        }
        __syncthreads();
    }

    if (MODE == 0) {
        // write raw dot products (float2 stores: base d_out+2 is 8B aligned)
#pragma unroll
        for (int i = 0; i < 8; i++) {
            int row = rowBase + ty * 8 + i;
            float* dst = Rout + (size_t)row * NMOD + colBase + tx * 8;
#pragma unroll
            for (int j = 0; j < 8; j += 2) {
                float2 v2 = make_float2(acc[i][j], acc[i][j + 1]);
                *reinterpret_cast<float2*>(dst + j) = v2;
            }
        }
    } else {
        // per-row max of acc * invc[col]; reduce across the 16 column threads
        int col0 = colBase + tx * 8;
        float ic[8];
#pragma unroll
        for (int j = 0; j < 8; j++) ic[j] = g_invc[col0 + j];
#pragma unroll
        for (int i = 0; i < 8; i++) {
            float m = acc[i][0] * ic[0];
#pragma unroll
            for (int j = 1; j < 8; j++) m = fmaxf(m, acc[i][j] * ic[j]);
            As[tx][ty * 8 + i] = m;      // reuse As as [16][128] reduce buffer
        }
        __syncthreads();
        if (tid < 128) {
            float m = As[0][tid];
#pragma unroll
            for (int x = 1; x < 16; x++) m = fmaxf(m, As[x][tid]);
            atomicMax(&g_negmax[rowBase + tid], fenc(m));
        }
    }
}

// ---------------- per-row stats + softmax rewrite in place ----------------
__global__ void row_stats_kernel(float* __restrict__ attn,
                                 float* __restrict__ perstep_out) {
    __shared__ float red[256];
    __shared__ float bc[4];
    const int row = blockIdx.x;
    const int tid = threadIdx.x;
    float* Rrow = attn + (size_t)row * NMOD;

    float v[16], ib[16];
#pragma unroll
    for (int q = 0; q < 16; q++) {
        int j = tid + q * 256;
        v[q]  = Rrow[j];        // coalesced
        ib[q] = g_invb[j];
    }

    float mr = -3.402823466e38f, mrb = -3.402823466e38f;
#pragma unroll
    for (int q = 0; q < 16; q++) {
        mr  = fmaxf(mr, v[q]);
        mrb = fmaxf(mrb, v[q] * ib[q]);
    }

    // reduce max of raw dots (for softmax shift)
    red[tid] = mr; __syncthreads();
    for (int off = 128; off > 0; off >>= 1) {
        if (tid < off) red[tid] = fmaxf(red[tid], red[tid + off]);
        __syncthreads();
    }
    if (tid == 0) bc[0] = red[0];
    __syncthreads();

    // reduce max of scaled dots (per-step cosine max)
    red[tid] = mrb; __syncthreads();
    for (int off = 128; off > 0; off >>= 1) {
        if (tid < off) red[tid] = fmaxf(red[tid], red[tid + off]);
        __syncthreads();
    }
    if (tid == 0) bc[1] = red[0];
    __syncthreads();

    const float maxR = bc[0];
    float e[16];
    float dsum = 0.0f, ws = 0.0f;
#pragma unroll
    for (int q = 0; q < 16; q++) {
        float ev = __expf((v[q] - maxR) * INVT);
        e[q] = ev;
        dsum += ev;
        ws   += v[q] * ib[q] * ev;
    }

    red[tid] = dsum; __syncthreads();
    for (int off = 128; off > 0; off >>= 1) {
        if (tid < off) red[tid] += red[tid + off];
        __syncthreads();
    }
    if (tid == 0) bc[2] = red[0];
    __syncthreads();

    red[tid] = ws; __syncthreads();
    for (int off = 128; off > 0; off >>= 1) {
        if (tid < off) red[tid] += red[tid + off];
        __syncthreads();
    }
    if (tid == 0) bc[3] = red[0];
    __syncthreads();

    const float invd = 1.0f / bc[2];
#pragma unroll
    for (int q = 0; q < 16; q++)
        Rrow[tid + q * 256] = e[q] * invd;     // attention, in place

    if (tid == 0) {
        float inva = g_inva[row];
        float ps = bc[1] * inva;
        g_perstep[row]  = ps;
        perstep_out[row] = ps;
        g_wsum[row] = inva * bc[3] * invd;
    }
}

// ---------------- final scalar reductions ----------------
__global__ void finalize_kernel(float* __restrict__ out) {
    __shared__ float r0[1024], r1[1024], r2[1024], r3[1024];
    const int tid = threadIdx.x;
    float s = 0.0f, mn = 3.402823466e38f, ws = 0.0f, ng = 0.0f;
#pragma unroll
    for (int q = 0; q < 8; q++) {
        int i = tid + q * 1024;
        float ps = g_perstep[i];
        s += ps;
        mn = fminf(mn, ps);
        ws += g_wsum[i];
        ng += fdec(g_negmax[i]) * g_inva[i];
    }
    r0[tid] = s; r1[tid] = mn; r2[tid] = ws; r3[tid] = ng;
    __syncthreads();
    for (int off = 512; off > 0; off >>= 1) {
        if (tid < off) {
            r0[tid] += r0[tid + off];
            r1[tid] = fminf(r1[tid], r1[tid + off]);
            r2[tid] += r2[tid + off];
            r3[tid] += r3[tid + off];
        }
        __syncthreads();
    }
    if (tid == 0) {
        float alignment = r0[0] * (1.0f / NSTEP);
        float weighted  = r2[0] * (1.0f / NSTEP);
        float neg       = r3[0] * (1.0f / NSTEP);
        float contrast  = alignment - neg;
        float margin    = fmaxf(contrast - 0.2f, 0.0f);
        float overall   = 0.7f * weighted + 0.3f * contrast;
        out[0] = alignment;          // alignment
        out[1] = weighted;           // weighted_alignment
        float* t = out + 2 + (size_t)NSTEP * NMOD;   // after attention
        t[0] = contrast;             // contrastive_score
        t[1] = margin;               // margin_score
        t[2] = alignment;            // positive_alignment
        t[3] = neg;                  // negative_alignment
        // per_step written by row_stats_kernel at t[4 .. 4+NSTEP)
        t[4 + NSTEP] = r1[0];        // min_step_coherence
        t[5 + NSTEP] = overall;      // overall
    }
}

// ---------------- launch ----------------
extern "C" void kernel_launch(void* const* d_in, const int* in_sizes, int n_in,
                              void* d_out, int out_size) {
    (void)in_sizes; (void)n_in; (void)out_size;
    const float* A = (const float*)d_in[0];   // step_embeddings  [8192,1024]
    const float* B = (const float*)d_in[1];   // modal_embeddings [4096,1024]
    const float* C = (const float*)d_in[2];   // negatives        [4096,1024]
    float* out  = (float*)d_out;
    float* attn = out + 2;                                   // attention slot
    float* perstep = out + 2 + (size_t)NSTEP * NMOD + 4;     // per_step slot

    init_kernel<<<(NSTEP + 255) / 256, 256>>>();
    inv_norm_kernel<0><<<NSTEP, 256>>>(A);
    inv_norm_kernel<1><<<NMOD, 256>>>(B);
    inv_norm_kernel<2><<<NMOD, 256>>>(C);

    dim3 g(NMOD / 128, NSTEP / 128);
    gemm_nt_kernel<0><<<g, 256>>>(A, B, attn);      // raw dots -> attention slot
    gemm_nt_kernel<1><<<g, 256>>>(A, C, nullptr);   // fused neg-max epilogue

    row_stats_kernel<<<NSTEP, 256>>>(attn, perstep);
    finalize_kernel<<<1, 1024>>>(out);
}